// round 16
// baseline (speedup 1.0000x reference)
#include <cuda_runtime.h>

#define NROWS 32768
#define DIM   128
#define NC    512
#define TOPK  10
#define MTILE 16
#define NTHR  256
#define NCAND 16
#define KSTRIDE 518                    // keys row stride (u32)

typedef unsigned long long u64;
typedef unsigned u32;

// smem layout (bytes)
#define XSTRIDE 132
#define BSTR    20                      // Bs row stride (u32; 16 data + 4 pad)
#define OFF_K    0                      // Bs [512][20] u32 = 40960 ; keys [16][518] u32 = 33152 overlays
#define OFF_XS   40960                  // xs [16][132] f32 = 8448
#define OFF_X2S  49408                  // [16] f32 (+pad) = 128
#define OFF_ML   49536                  // [16][4][16] u32 = 4096
#define OFF_CAND 53632                  // [16][16] i32 = 1024
#define OFF_EX   54656                  // [16][16] u64 = 2048
#define SMEM_TOTAL 56704                // x4 = 226.8KB -> 4 CTAs/SM

__device__ float g_c2[NC];
__device__ u32   g_cc_bf16[NC * DIM / 2];    // [c][k/2] packed bf16x2
__device__ int   g_fidx[NROWS * TOPK];

// XLA GPU row-reduction for sum(v*v) — empirically bit-exact vs reference. DO NOT CHANGE.
__device__ __forceinline__ float xla_row_sumsq(const float* __restrict__ row, int lane) {
    float4 v = *reinterpret_cast<const float4*>(row + 4 * lane);
    float p = __fmul_rn(v.x, v.x);
    p = __fadd_rn(p, __fmul_rn(v.y, v.y));
    p = __fadd_rn(p, __fmul_rn(v.z, v.z));
    p = __fadd_rn(p, __fmul_rn(v.w, v.w));
#pragma unroll
    for (int off = 16; off > 0; off >>= 1)
        p = __fadd_rn(p, __shfl_down_sync(0xffffffffu, p, off));
    return __shfl_sync(0xffffffffu, p, 0);
}

__device__ __forceinline__ u32 pack_bf16(float lo, float hi) {
    u32 o;
    asm("cvt.rn.bf16x2.f32 %0, %1, %2;" : "=r"(o) : "f"(hi), "f"(lo));
    return o;
}

__global__ void c2_kernel(const float* __restrict__ cc) {
    int warp = threadIdx.x >> 5;
    int lane = threadIdx.x & 31;
    int c = blockIdx.x * 8 + warp;
    float s = xla_row_sumsq(cc + (size_t)c * DIM, lane);
    if (lane == 0) g_c2[c] = s;
#pragma unroll
    for (int j = 0; j < 2; ++j) {
        int k2 = lane + 32 * j;
        g_cc_bf16[c * 64 + k2] = pack_bf16(cc[(size_t)c * DIM + 2 * k2],
                                           cc[(size_t)c * DIM + 2 * k2 + 1]);
    }
}

__device__ __forceinline__ void mma_bf16(float& d0, float& d1, float& d2, float& d3,
                                         u32 a0, u32 a1, u32 a2, u32 a3,
                                         u32 b0, u32 b1) {
    asm("mma.sync.aligned.m16n8k16.row.col.f32.bf16.bf16.f32 "
        "{%0,%1,%2,%3}, {%4,%5,%6,%7}, {%8,%9}, {%0,%1,%2,%3};"
        : "+f"(d0), "+f"(d1), "+f"(d2), "+f"(d3)
        : "r"(a0), "r"(a1), "r"(a2), "r"(a3), "r"(b0), "r"(b1));
}

__device__ __forceinline__ u32 ford(float f) {
    u32 u = __float_as_uint(f);
    return (u & 0x80000000u) ? ~u : (u | 0x80000000u);
}

__global__ __launch_bounds__(NTHR, 4)
void kmeans_topk_kernel(const float* __restrict__ x,
                        const float* __restrict__ cc) {
    extern __shared__ char smraw[];
    u32*   Bs   = reinterpret_cast<u32*>(smraw + OFF_K);     // [512][20]
    u32*   keys = reinterpret_cast<u32*>(smraw + OFF_K);     // overlay [16][518]
    float* xs   = reinterpret_cast<float*>(smraw + OFF_XS);  // [16][132]
    float* x2s  = reinterpret_cast<float*>(smraw + OFF_X2S); // [16]
    u32*   ML   = reinterpret_cast<u32*>(smraw + OFF_ML);    // [16][4][16]
    int*   CAND = reinterpret_cast<int*>(smraw + OFF_CAND);  // [16][16]
    u64*   EX   = reinterpret_cast<u64*>(smraw + OFF_EX);    // [16][16]

    const int tx   = threadIdx.x;
    const int row0 = blockIdx.x * MTILE;
    const int lane = tx & 31;
    const int warp = tx >> 5;     // 0..7
    const int nq   = warp;        // 64 centers each
    const int g    = lane >> 2;   // 0..7
    const int t    = lane & 3;    // 0..3

    // ---- stage exact x tile [16][128] ----
    {
        const float4* x4 = reinterpret_cast<const float4*>(x) + (size_t)row0 * 32;
#pragma unroll
        for (int j = 0; j < 2; ++j) {
            int i = tx + NTHR * j;         // 0..511
            int r = i >> 5, kq = i & 31;
            *reinterpret_cast<float4*>(xs + r * XSTRIDE + kq * 4) = x4[i];
        }
    }
    // ---- x2[row] exact XLA order; warp w does rows w and w+8 ----
#pragma unroll
    for (int j = 0; j < 2; ++j) {
        int rl = warp + 8 * j;
        float s = xla_row_sumsq(x + (size_t)(row0 + rl) * DIM, lane);
        if (lane == 0) x2s[rl] = s;
    }

    // ---- bf16 filter GEMM: per warp 16 rows x 64 centers, m16n8k16 ----
    float acc[8][4];
#pragma unroll
    for (int nt = 0; nt < 8; ++nt)
#pragma unroll
        for (int j = 0; j < 4; ++j) acc[nt][j] = 0.0f;

    for (int ktc = 0; ktc < 4; ++ktc) {
        __syncthreads();
        // B tile: 512 c x 16 u32 (bf16x2) -> Bs stride 20
#pragma unroll
        for (int j = 0; j < 8; ++j) {
            int i = tx + NTHR * j;         // 0..2047
            int c = i >> 2, q = i & 3;
            uint4 v = *reinterpret_cast<const uint4*>(g_cc_bf16 + c * 64 + ktc * 16 + q * 4);
            *reinterpret_cast<uint4*>(Bs + c * BSTR + q * 4) = v;
        }
        __syncthreads();
#pragma unroll
        for (int sp = 0; sp < 2; ++sp) {
            const int k0 = ktc * 32 + sp * 16;
            float2 va = *reinterpret_cast<const float2*>(xs + g * XSTRIDE + k0 + 2 * t);
            float2 vb = *reinterpret_cast<const float2*>(xs + (g + 8) * XSTRIDE + k0 + 2 * t);
            float2 vc = *reinterpret_cast<const float2*>(xs + g * XSTRIDE + k0 + 8 + 2 * t);
            float2 vd = *reinterpret_cast<const float2*>(xs + (g + 8) * XSTRIDE + k0 + 8 + 2 * t);
            u32 a0 = pack_bf16(va.x, va.y);
            u32 a1 = pack_bf16(vb.x, vb.y);
            u32 a2 = pack_bf16(vc.x, vc.y);
            u32 a3 = pack_bf16(vd.x, vd.y);
#pragma unroll
            for (int nt = 0; nt < 8; ++nt) {
                const u32* bp = Bs + (nq * 64 + nt * 8 + g) * BSTR + sp * 8 + t;
                mma_bf16(acc[nt][0], acc[nt][1], acc[nt][2], acc[nt][3],
                         a0, a1, a2, a3, bp[0], bp[4]);
            }
        }
    }
    __syncthreads();

    // ---- epilogue: u32 keys = (ford(c2 - 2*dot) & ~511) | c ----
#pragma unroll
    for (int nt = 0; nt < 8; ++nt) {
        int c0 = nq * 64 + nt * 8 + 2 * t;
        float c2lo = __ldg(&g_c2[c0]), c2hi = __ldg(&g_c2[c0 + 1]);
        int ra = g * KSTRIDE, rbx = (g + 8) * KSTRIDE;
        uint2 ka, kb;
        ka.x = (ford(c2lo - 2.0f * acc[nt][0]) & ~511u) | (u32)c0;
        ka.y = (ford(c2hi - 2.0f * acc[nt][1]) & ~511u) | (u32)(c0 + 1);
        kb.x = (ford(c2lo - 2.0f * acc[nt][2]) & ~511u) | (u32)c0;
        kb.y = (ford(c2hi - 2.0f * acc[nt][3]) & ~511u) | (u32)(c0 + 1);
        *reinterpret_cast<uint2*>(keys + ra + c0) = ka;
        *reinterpret_cast<uint2*>(keys + rbx + c0) = kb;
    }
    __syncthreads();

    // ---- filter: 16 threads/row, top-16 of 32 keys each; write back sorted ----
    {
        const int rl = tx >> 4;
        const int j = tx & 15;
        const int base = rl * KSTRIDE + 32 * j;
        const int rot = (j + 13 * (rl & 1)) & 31;
        u32 bs[NCAND];
#pragma unroll
        for (int p = 0; p < NCAND; ++p) bs[p] = 0xFFFFFFFFu;
        for (int v = 0; v < 32; ++v) {
            u32 k = keys[base + ((v + rot) & 31)];
            if (k < bs[NCAND - 1]) {
                bs[NCAND - 1] = k;
#pragma unroll
                for (int p = NCAND - 1; p > 0; --p)
                    if (bs[p] < bs[p - 1]) { u32 tm = bs[p]; bs[p] = bs[p - 1]; bs[p - 1] = tm; }
            }
        }
#pragma unroll
        for (int p = 0; p < NCAND; ++p) keys[base + p] = bs[p];
    }
    __syncthreads();

    // ---- merge stage 1: 4 threads/row, 4-way sorted merge -> 16 ----
    if (tx < 64) {
        const int rl = tx >> 2;
        const int q = tx & 3;
        const u32* L = keys + rl * KSTRIDE + 32 * (4 * q);
        int p0 = 0, p1 = 0, p2 = 0, p3 = 0;
        u32 h0 = L[0], h1 = L[32], h2 = L[64], h3 = L[96];
        u32* outp = ML + rl * 64 + q * 16;
#pragma unroll
        for (int m = 0; m < NCAND; ++m) {
            u32 mn = h0; int a = 0;
            if (h1 < mn) { mn = h1; a = 1; }
            if (h2 < mn) { mn = h2; a = 2; }
            if (h3 < mn) { mn = h3; a = 3; }
            outp[m] = mn;
            if (a == 0)      { ++p0; h0 = (p0 < 16) ? L[p0]      : 0xFFFFFFFFu; }
            else if (a == 1) { ++p1; h1 = (p1 < 16) ? L[32 + p1] : 0xFFFFFFFFu; }
            else if (a == 2) { ++p2; h2 = (p2 < 16) ? L[64 + p2] : 0xFFFFFFFFu; }
            else             { ++p3; h3 = (p3 < 16) ? L[96 + p3] : 0xFFFFFFFFu; }
        }
    }
    __syncthreads();

    // ---- merge stage 2: 1 thread/row -> 16 candidate centers ----
    if (tx < MTILE) {
        const int rl = tx;
        const u32* L = ML + rl * 64;
        int p0 = 0, p1 = 0, p2 = 0, p3 = 0;
        u32 h0 = L[0], h1 = L[16], h2 = L[32], h3 = L[48];
#pragma unroll
        for (int m = 0; m < NCAND; ++m) {
            u32 mn = h0; int a = 0;
            if (h1 < mn) { mn = h1; a = 1; }
            if (h2 < mn) { mn = h2; a = 2; }
            if (h3 < mn) { mn = h3; a = 3; }
            CAND[rl * NCAND + m] = (int)(mn & 511u);
            if (a == 0)      { ++p0; h0 = (p0 < 16) ? L[p0]      : 0xFFFFFFFFu; }
            else if (a == 1) { ++p1; h1 = (p1 < 16) ? L[16 + p1] : 0xFFFFFFFFu; }
            else if (a == 2) { ++p2; h2 = (p2 < 16) ? L[32 + p2] : 0xFFFFFFFFu; }
            else             { ++p3; h3 = (p3 < 16) ? L[48 + p3] : 0xFFFFFFFFu; }
        }
    }
    __syncthreads();

    // ---- exact rescore: 1 thread per (row, candidate) — bit-exact reference chain ----
    {
        const int rl = tx >> 4;
        const int sidx = tx & 15;
        const int c = CAND[rl * NCAND + sidx];
        const float4* cp = reinterpret_cast<const float4*>(cc + (size_t)c * DIM);
        const float4* xp = reinterpret_cast<const float4*>(xs + rl * XSTRIDE);
        float s = 0.0f;
        // sequential ascending-k FMA chain (matches cublas per-element order)
#pragma unroll 8
        for (int q = 0; q < 32; ++q) {
            float4 cv = __ldg(cp + q);
            float4 xv = xp[q];
            s = __fmaf_rn(xv.x, cv.x, s);
            s = __fmaf_rn(xv.y, cv.y, s);
            s = __fmaf_rn(xv.z, cv.z, s);
            s = __fmaf_rn(xv.w, cv.w, s);
        }
        float u = __fadd_rn(__fsub_rn(x2s[rl], 2.0f * s), __ldg(&g_c2[c]));
        float d = __fsqrt_rn(fmaxf(u, 0.0f));
        EX[rl * NCAND + sidx] = ((u64)__float_as_uint(d) << 32) | (u32)c;
    }
    __syncthreads();

    // ---- exact keyed top-10 of 16 per row -> global fidx ----
    if (tx < MTILE) {
        const int rl = tx;
        u64 bs[TOPK];
#pragma unroll
        for (int p = 0; p < TOPK; ++p) bs[p] = ~0ull;
#pragma unroll
        for (int v = 0; v < NCAND; ++v) {
            u64 key = EX[rl * NCAND + v];
            if (key < bs[TOPK - 1]) {
                bs[TOPK - 1] = key;
#pragma unroll
                for (int p = TOPK - 1; p > 0; --p)
                    if (bs[p] < bs[p - 1]) { u64 tm = bs[p]; bs[p] = bs[p - 1]; bs[p - 1] = tm; }
            }
        }
#pragma unroll
        for (int p = 0; p < TOPK; ++p)
            g_fidx[(size_t)(row0 + rl) * TOPK + p] = (int)(u32)(bs[p] & 0xffffffffu);
    }
}

// ---- dedicated gather: out[orow] = x[fidx[orow]], fully coalesced streaming ----
__global__ __launch_bounds__(256)
void gather_kernel(const float* __restrict__ x, float* __restrict__ out) {
    const float4* x4 = reinterpret_cast<const float4*>(x);
    float4* out4 = reinterpret_cast<float4*>(out);
    size_t i = (size_t)blockIdx.x * (256 * 20) + threadIdx.x;
#pragma unroll
    for (int it = 0; it < 20; ++it, i += 256) {
        size_t orow = i >> 5;
        int e = (int)(i & 31);
        int idx = g_fidx[orow];
        out4[i] = __ldg(&x4[(size_t)idx * 32 + e]);
    }
}

extern "C" void kernel_launch(void* const* d_in, const int* in_sizes, int n_in,
                              void* d_out, int out_size) {
    const float* x  = (const float*)d_in[0];
    const float* cc = (const float*)d_in[1];
    float* out = (float*)d_out;

    cudaFuncSetAttribute(kmeans_topk_kernel,
                         cudaFuncAttributeMaxDynamicSharedMemorySize, SMEM_TOTAL);
    c2_kernel<<<NC / 8, 256>>>(cc);
    kmeans_topk_kernel<<<NROWS / MTILE, NTHR, SMEM_TOTAL>>>(x, cc);
    gather_kernel<<<2048, 256>>>(x, out);
}